// round 7
// baseline (speedup 1.0000x reference)
#include <cuda_runtime.h>
#include <cuda_bf16.h>

#define DT_F      0.01f
#define DT_D      0.01
#define MIN_VAR   0.01f
#define REG_W     0.01
#define EPS_L     1e-6f
#define BATCH     256
#define TLEN      16384
#define NTHR      256          // threads per CTA
#define EPT       4            // float2 elements (timesteps) per thread
#define SEG       (NTHR*EPT)   // 1024 timesteps per segment
#define NSEG      (TLEN/SEG)   // 16 segments per row
#define NGRID     (BATCH*NSEG) // 4096 CTAs

// Per-segment records, laid out [seg][row] so the tail phase reads coalesced.
// recA = (sum_vel.x, sum_vel.y, sum_a.x, sum_a.y)
// recB = (sum_a2, lve, lcs, rgs)
__device__ float4 g_recA[NGRID];
__device__ float4 g_recB[NGRID];
__device__ int    g_cnt = 0;   // self-resetting completion counter

__global__ __launch_bounds__(NTHR)
void mtl_fused_kernel(const float4* __restrict__ vel4,
                      const float4* __restrict__ cov4,
                      const float4* __restrict__ vgt4,
                      const float4* __restrict__ pgt4,
                      const float2* __restrict__ vel2,   // for v0 broadcast
                      const float*  __restrict__ log_dv_p,
                      const float*  __restrict__ log_dc_p,
                      float* __restrict__ out)
{
    __shared__ float2 wsum[8];          // per-warp vel totals
    __shared__ float  sred[8][6];       // phase-1 block reduction
    __shared__ double dred[8][4];       // phase-2 block reduction
    __shared__ int    s_last;

    const int row  = blockIdx.x & (BATCH - 1);
    const int seg  = blockIdx.x >> 8;           // 0..15
    const int tid  = threadIdx.x;
    const int lane = tid & 31;
    const int wid  = tid >> 5;

    // float4 index of this thread's 4 timesteps (2 float4 = 4 float2 elems)
    const long f4base = ((long)row * TLEN + (long)seg * SEG) / 2 + (long)tid * 2;

    // ---- issue all 8 loads up front (MLP=8) ----
    const float4 va = vel4[f4base];
    const float4 vb = vel4[f4base + 1];
    const float4 ca = cov4[f4base];
    const float4 cb = cov4[f4base + 1];
    const float4 ga = vgt4[f4base];
    const float4 gb = vgt4[f4base + 1];
    const float4 pa = pgt4[f4base];
    const float4 pb = pgt4[f4base + 1];

    const float2 v0 = vel2[(long)row * TLEN];   // broadcast load

    // thread-local vel elements: (x,y) pairs
    const float vx[EPT] = {va.x, va.z, vb.x, vb.z};
    const float vy[EPT] = {va.y, va.w, vb.y, vb.w};

    // ---- block scan of per-thread vel sums ----
    float tsx = vx[0] + vx[1] + vx[2] + vx[3];
    float tsy = vy[0] + vy[1] + vy[2] + vy[3];
    float ix = tsx, iy = tsy;                   // inclusive within warp
    #pragma unroll
    for (int off = 1; off < 32; off <<= 1) {
        float nx = __shfl_up_sync(0xffffffffu, ix, off);
        float ny = __shfl_up_sync(0xffffffffu, iy, off);
        if (lane >= off) { ix += nx; iy += ny; }
    }
    if (lane == 31) wsum[wid] = make_float2(ix, iy);
    __syncthreads();
    if (wid == 0 && lane < 8) {
        float sx = wsum[lane].x, sy = wsum[lane].y;
        #pragma unroll
        for (int off = 1; off < 8; off <<= 1) {
            float nx = __shfl_up_sync(0xffu, sx, off);
            float ny = __shfl_up_sync(0xffu, sy, off);
            if (lane >= off) { sx += nx; sy += ny; }
        }
        wsum[lane] = make_float2(sx, sy);
    }
    __syncthreads();

    // exclusive prefix (within segment) entering this thread's first element
    float ex = (wid > 0 ? wsum[wid - 1].x : 0.0f) + (ix - tsx);
    float ey = (wid > 0 ? wsum[wid - 1].y : 0.0f) + (iy - tsy);
    const float2 segsum = wsum[7];              // segment vel total

    // ---- per-element math ----
    const float cx_[EPT] = {ca.x, ca.z, cb.x, cb.z};
    const float cy_[EPT] = {ca.y, ca.w, cb.y, cb.w};
    const float gx_[EPT] = {ga.x, ga.z, gb.x, gb.z};
    const float gy_[EPT] = {ga.y, ga.w, gb.y, gb.w};
    const float px_[EPT] = {pa.x, pa.z, pb.x, pb.z};
    const float py_[EPT] = {pa.y, pa.w, pb.y, pb.w};

    float sax = 0.f, say = 0.f, sa2 = 0.f;
    float lve = 0.f, lcs = 0.f, rgs = 0.f;

    #pragma unroll
    for (int i = 0; i < EPT; ++i) {
        // a = DT*(v0 + local_excl) - pos_gt   (global carry added in tail phase)
        const float ax = DT_F * (v0.x + ex) - px_[i];
        const float ay = DT_F * (v0.y + ey) - py_[i];
        sax += ax; say += ay;
        sa2 += ax * ax + ay * ay;
        ex += vx[i]; ey += vy[i];

        const float dvx = vx[i] - gx_[i];
        const float dvy = vy[i] - gy_[i];
        lve += dvx * dvx + dvy * dvy;

        const float sgx = fmaxf(__expf(cx_[i]), MIN_VAR);
        const float sgy = fmaxf(__expf(cy_[i]), MIN_VAR);
        const float ivx = __frcp_rn(sgx);
        const float ivy = __frcp_rn(sgy);
        lcs += ivx * dvx * dvx + ivy * dvy * dvy + __logf(sgx * sgy + EPS_L);
        rgs += ivx + ivy;
    }

    // ---- block reduce 6 floats ----
    float r[6] = {sax, say, sa2, lve, lcs, rgs};
    #pragma unroll
    for (int off = 16; off > 0; off >>= 1) {
        #pragma unroll
        for (int k = 0; k < 6; ++k)
            r[k] += __shfl_down_sync(0xffffffffu, r[k], off);
    }
    if (lane == 0) {
        #pragma unroll
        for (int k = 0; k < 6; ++k) sred[wid][k] = r[k];
    }
    __syncthreads();
    if (tid == 0) {
        #pragma unroll
        for (int k = 0; k < 6; ++k) {
            float s = sred[0][k];
            #pragma unroll
            for (int w = 1; w < 8; ++w) s += sred[w][k];
            r[k] = s;
        }
        const int ri = seg * BATCH + row;       // [seg][row] layout
        g_recA[ri] = make_float4(segsum.x, segsum.y, r[0], r[1]);
        g_recB[ri] = make_float4(r[2], r[3], r[4], r[5]);
        __threadfence();
        const int done = atomicAdd(&g_cnt, 1);
        s_last = (done == NGRID - 1);
    }
    __syncthreads();

    if (!s_last) return;

    // ================= tail phase: one block, carry recombination =================
    __threadfence();                            // acquire all records
    {
        const int myrow = tid;                  // 256 threads = 256 rows
        double cxd = 0.0, cyd = 0.0;
        double lvp_d = 0.0, lve_d = 0.0, lcs_d = 0.0, rgs_d = 0.0;
        #pragma unroll 1
        for (int s = 0; s < NSEG; ++s) {
            const float4 ra = g_recA[s * BATCH + myrow];   // coalesced
            const float4 rb = g_recB[s * BATCH + myrow];
            // sum over segment of (a + DT*c)^2, both components
            lvp_d += (double)rb.x
                   + 2.0 * DT_D * (cxd * (double)ra.z + cyd * (double)ra.w)
                   + (double)SEG * DT_D * DT_D * (cxd * cxd + cyd * cyd);
            lve_d += (double)rb.y;
            lcs_d += (double)rb.z;
            rgs_d += (double)rb.w;
            cxd += (double)ra.x;
            cyd += (double)ra.y;
        }

        double d[4] = {lvp_d, lve_d, lcs_d, rgs_d};
        #pragma unroll
        for (int off = 16; off > 0; off >>= 1) {
            #pragma unroll
            for (int k = 0; k < 4; ++k)
                d[k] += __shfl_down_sync(0xffffffffu, d[k], off);
        }
        if (lane == 0) {
            #pragma unroll
            for (int k = 0; k < 4; ++k) dred[wid][k] = d[k];
        }
        __syncthreads();
        if (tid == 0) {
            #pragma unroll
            for (int k = 0; k < 4; ++k) {
                double s = dred[0][k];
                #pragma unroll
                for (int w = 1; w < 8; ++w) s += dred[w][k];
                d[k] = s;
            }
            const double n_all = (double)BATCH * (double)TLEN * 2.0;
            const double n_bt  = (double)BATCH * (double)TLEN;
            const float  ldv = *log_dv_p;
            const float  ldc = *log_dc_p;
            const double dv  = exp((double)ldv);
            const double dc  = exp((double)ldc);

            const double lv_total = (d[0] + d[1]) / n_all;
            const double lc_total = 0.5 * (d[2] / n_bt);
            const double reg      = d[3] / n_bt;

            double total = lv_total / (2.0 * dv * dv)
                         + lc_total / (2.0 * dc * dc)
                         + (double)ldv + (double)ldc
                         + REG_W * reg;
            *out = (float)total;
            g_cnt = 0;                          // reset for next graph replay
        }
    }
}

extern "C" void kernel_launch(void* const* d_in, const int* in_sizes, int n_in,
                              void* d_out, int out_size)
{
    const float4* vel4 = (const float4*)d_in[0];
    const float4* cov4 = (const float4*)d_in[1];
    const float4* vgt4 = (const float4*)d_in[2];
    const float4* pgt4 = (const float4*)d_in[3];
    const float2* vel2 = (const float2*)d_in[0];
    const float*  ldv  = (const float*)d_in[4];
    const float*  ldc  = (const float*)d_in[5];
    float* out = (float*)d_out;

    mtl_fused_kernel<<<NGRID, NTHR>>>(vel4, cov4, vgt4, pgt4, vel2, ldv, ldc, out);
}

// round 8
// speedup vs baseline: 1.1073x; 1.1073x over previous
#include <cuda_runtime.h>
#include <cuda_bf16.h>

#define DT_F      0.01f
#define DT_D      0.01
#define REG_W     0.01
#define EPS_L     1e-6f
#define LN_MINVAR (-4.6051702f)   // ln(0.01)
#define BATCH     256
#define TLEN      16384
#define NTHR      256             // threads per CTA
#define EPT       8               // timesteps per thread
#define F4PT      (EPT/2)         // float4 loads per array per thread (4)
#define SEG       (NTHR*EPT)      // 2048 timesteps per segment
#define NSEG      (TLEN/SEG)      // 8 segments per row
#define NGRID     (BATCH*NSEG)    // 2048 CTAs

// Per-segment records, [seg][row] so tail reads coalesced.
// recA = (sum_vel.x, sum_vel.y, sum_a.x, sum_a.y)
// recB = (sum_a2, lve, lcs, rgs)
__device__ float4 g_recA[NGRID];
__device__ float4 g_recB[NGRID];
__device__ int    g_cnt = 0;      // self-resetting completion counter

__global__ __launch_bounds__(NTHR)
void mtl_fused_kernel(const float4* __restrict__ vel4,
                      const float4* __restrict__ cov4,
                      const float4* __restrict__ vgt4,
                      const float4* __restrict__ pgt4,
                      const float2* __restrict__ vel2,
                      const float*  __restrict__ log_dv_p,
                      const float*  __restrict__ log_dc_p,
                      float* __restrict__ out)
{
    __shared__ float2 wsum[8];
    __shared__ float  sred[8][6];
    __shared__ double dred[8][4];
    __shared__ int    s_last;

    const int row  = blockIdx.x & (BATCH - 1);
    const int seg  = blockIdx.x >> 8;            // 0..NSEG-1
    const int tid  = threadIdx.x;
    const int lane = tid & 31;
    const int wid  = tid >> 5;

    // float4 index of this thread's EPT consecutive timesteps
    const long f4base = ((long)row * TLEN + (long)seg * SEG) / 2 + (long)tid * F4PT;

    // ---- issue ALL 16 loads up front (MLP=16 per thread) ----
    float4 va[F4PT], ca[F4PT], ga[F4PT], pa[F4PT];
    #pragma unroll
    for (int i = 0; i < F4PT; ++i) va[i] = vel4[f4base + i];
    #pragma unroll
    for (int i = 0; i < F4PT; ++i) ca[i] = cov4[f4base + i];
    #pragma unroll
    for (int i = 0; i < F4PT; ++i) ga[i] = vgt4[f4base + i];
    #pragma unroll
    for (int i = 0; i < F4PT; ++i) pa[i] = pgt4[f4base + i];

    const float2 v0 = vel2[(long)row * TLEN];    // broadcast

    // ---- per-thread vel sum, then block scan of thread sums ----
    float tsx = 0.f, tsy = 0.f;
    #pragma unroll
    for (int i = 0; i < F4PT; ++i) { tsx += va[i].x + va[i].z; tsy += va[i].y + va[i].w; }

    float ixp = tsx, iyp = tsy;                  // inclusive within warp
    #pragma unroll
    for (int off = 1; off < 32; off <<= 1) {
        float nx = __shfl_up_sync(0xffffffffu, ixp, off);
        float ny = __shfl_up_sync(0xffffffffu, iyp, off);
        if (lane >= off) { ixp += nx; iyp += ny; }
    }
    if (lane == 31) wsum[wid] = make_float2(ixp, iyp);
    __syncthreads();
    if (wid == 0 && lane < 8) {
        float sx = wsum[lane].x, sy = wsum[lane].y;
        #pragma unroll
        for (int off = 1; off < 8; off <<= 1) {
            float nx = __shfl_up_sync(0xffu, sx, off);
            float ny = __shfl_up_sync(0xffu, sy, off);
            if (lane >= off) { sx += nx; sy += ny; }
        }
        wsum[lane] = make_float2(sx, sy);
    }
    __syncthreads();

    // exclusive prefix (within segment) entering this thread's first element
    float ex = (wid > 0 ? wsum[wid - 1].x : 0.0f) + (ixp - tsx);
    float ey = (wid > 0 ? wsum[wid - 1].y : 0.0f) + (iyp - tsy);
    const float2 segsum = wsum[7];

    // ---- per-element math (2 MUFU per timestep, no RCP, no LG2) ----
    float sax = 0.f, say = 0.f, sa2 = 0.f;
    float lve = 0.f, lcs = 0.f, rgs = 0.f;

    #pragma unroll
    for (int i = 0; i < EPT; ++i) {
        const int   q  = i >> 1;
        const bool  hi = (i & 1);
        const float vx = hi ? va[q].z : va[q].x;
        const float vy = hi ? va[q].w : va[q].y;
        const float cx = hi ? ca[q].z : ca[q].x;
        const float cy = hi ? ca[q].w : ca[q].y;
        const float gx = hi ? ga[q].z : ga[q].x;
        const float gy = hi ? ga[q].w : ga[q].y;
        const float px = hi ? pa[q].z : pa[q].x;
        const float py = hi ? pa[q].w : pa[q].y;

        // a = DT*(v0 + local_excl) - pos_gt (global carry added in tail)
        const float ax = DT_F * (v0.x + ex) - px;
        const float ay = DT_F * (v0.y + ey) - py;
        sax += ax; say += ay;
        sa2 += ax * ax + ay * ay;
        ex += vx; ey += vy;

        const float dvx = vx - gx;
        const float dvy = vy - gy;
        lve += dvx * dvx + dvy * dvy;

        // inv_sigma = 1/clip(exp(c),0.01) = min(exp(-c), 100)
        const float ivx = fminf(__expf(-cx), 100.0f);
        const float ivy = fminf(__expf(-cy), 100.0f);
        // log(sx*sy + eps) = max(cx,ln.01)+max(cy,ln.01) + log1p(u), u=eps*ivx*ivy
        const float u = EPS_L * ivx * ivy;
        const float logdet = fmaxf(cx, LN_MINVAR) + fmaxf(cy, LN_MINVAR)
                           + u * (1.0f - 0.5f * u);
        lcs += ivx * dvx * dvx + ivy * dvy * dvy + logdet;
        rgs += ivx + ivy;
    }

    // ---- block reduce 6 floats ----
    float r[6] = {sax, say, sa2, lve, lcs, rgs};
    #pragma unroll
    for (int off = 16; off > 0; off >>= 1) {
        #pragma unroll
        for (int k = 0; k < 6; ++k)
            r[k] += __shfl_down_sync(0xffffffffu, r[k], off);
    }
    if (lane == 0) {
        #pragma unroll
        for (int k = 0; k < 6; ++k) sred[wid][k] = r[k];
    }
    __syncthreads();
    if (tid == 0) {
        #pragma unroll
        for (int k = 0; k < 6; ++k) {
            float s = sred[0][k];
            #pragma unroll
            for (int w = 1; w < 8; ++w) s += sred[w][k];
            r[k] = s;
        }
        const int ri = seg * BATCH + row;
        g_recA[ri] = make_float4(segsum.x, segsum.y, r[0], r[1]);
        g_recB[ri] = make_float4(r[2], r[3], r[4], r[5]);
        __threadfence();
        const int done = atomicAdd(&g_cnt, 1);
        s_last = (done == NGRID - 1);
    }
    __syncthreads();

    if (!s_last) return;

    // ================= tail: one block, fp64 carry recombination =================
    __threadfence();
    {
        const int myrow = tid;                   // 256 threads = 256 rows
        double cxd = 0.0, cyd = 0.0;
        double lvp_d = 0.0, lve_d = 0.0, lcs_d = 0.0, rgs_d = 0.0;
        #pragma unroll 1
        for (int s = 0; s < NSEG; ++s) {
            const float4 ra = g_recA[s * BATCH + myrow];
            const float4 rb = g_recB[s * BATCH + myrow];
            lvp_d += (double)rb.x
                   + 2.0 * DT_D * (cxd * (double)ra.z + cyd * (double)ra.w)
                   + (double)SEG * DT_D * DT_D * (cxd * cxd + cyd * cyd);
            lve_d += (double)rb.y;
            lcs_d += (double)rb.z;
            rgs_d += (double)rb.w;
            cxd += (double)ra.x;
            cyd += (double)ra.y;
        }

        double d[4] = {lvp_d, lve_d, lcs_d, rgs_d};
        #pragma unroll
        for (int off = 16; off > 0; off >>= 1) {
            #pragma unroll
            for (int k = 0; k < 4; ++k)
                d[k] += __shfl_down_sync(0xffffffffu, d[k], off);
        }
        if (lane == 0) {
            #pragma unroll
            for (int k = 0; k < 4; ++k) dred[wid][k] = d[k];
        }
        __syncthreads();
        if (tid == 0) {
            #pragma unroll
            for (int k = 0; k < 4; ++k) {
                double s = dred[0][k];
                #pragma unroll
                for (int w = 1; w < 8; ++w) s += dred[w][k];
                d[k] = s;
            }
            const double n_all = (double)BATCH * (double)TLEN * 2.0;
            const double n_bt  = (double)BATCH * (double)TLEN;
            const float  ldv = *log_dv_p;
            const float  ldc = *log_dc_p;
            const double dv  = exp((double)ldv);
            const double dc  = exp((double)ldc);

            const double lv_total = (d[0] + d[1]) / n_all;
            const double lc_total = 0.5 * (d[2] / n_bt);
            const double reg      = d[3] / n_bt;

            double total = lv_total / (2.0 * dv * dv)
                         + lc_total / (2.0 * dc * dc)
                         + (double)ldv + (double)ldc
                         + REG_W * reg;
            *out = (float)total;
            g_cnt = 0;
        }
    }
}

extern "C" void kernel_launch(void* const* d_in, const int* in_sizes, int n_in,
                              void* d_out, int out_size)
{
    const float4* vel4 = (const float4*)d_in[0];
    const float4* cov4 = (const float4*)d_in[1];
    const float4* vgt4 = (const float4*)d_in[2];
    const float4* pgt4 = (const float4*)d_in[3];
    const float2* vel2 = (const float2*)d_in[0];
    const float*  ldv  = (const float*)d_in[4];
    const float*  ldc  = (const float*)d_in[5];
    float* out = (float*)d_out;

    mtl_fused_kernel<<<NGRID, NTHR>>>(vel4, cov4, vgt4, pgt4, vel2, ldv, ldc, out);
}

// round 9
// speedup vs baseline: 1.1567x; 1.0446x over previous
#include <cuda_runtime.h>
#include <cuda_bf16.h>

#define DT_F      0.01f
#define DT_D      0.01
#define REG_W     0.01
#define EPS_L     1e-6f
#define LN_MINVAR (-4.6051702f)   // ln(0.01)
#define BATCH     256
#define TLEN      16384
#define NTHR      512             // threads per CTA
#define NWARP     (NTHR/32)       // 16
#define EPT       4               // timesteps per thread
#define F4PT      (EPT/2)         // float4 loads per array per thread (2)
#define SEG       (NTHR*EPT)      // 2048 timesteps per segment
#define NSEG      (TLEN/SEG)      // 8 segments per row
#define NGRID     (BATCH*NSEG)    // 2048 CTAs

// Per-segment records, [seg][row] so tail reads coalesced.
// recA = (sum_vel.x, sum_vel.y, sum_a.x, sum_a.y)
// recB = (sum_a2, lve, lcs, rgs)
__device__ float4 g_recA[NGRID];
__device__ float4 g_recB[NGRID];
__device__ int    g_cnt = 0;      // self-resetting completion counter

__global__ __launch_bounds__(NTHR, 2)
void mtl_fused_kernel(const float4* __restrict__ vel4,
                      const float4* __restrict__ cov4,
                      const float4* __restrict__ vgt4,
                      const float4* __restrict__ pgt4,
                      const float2* __restrict__ vel2,
                      const float*  __restrict__ log_dv_p,
                      const float*  __restrict__ log_dc_p,
                      float* __restrict__ out)
{
    __shared__ float2 wsum[NWARP];
    __shared__ float  sred[NWARP][6];
    __shared__ double dred[NWARP][4];
    __shared__ int    s_last;

    const int row  = blockIdx.x & (BATCH - 1);
    const int seg  = blockIdx.x >> 8;            // 0..NSEG-1
    const int tid  = threadIdx.x;
    const int lane = tid & 31;
    const int wid  = tid >> 5;

    // float4 index of this thread's EPT consecutive timesteps
    const long f4base = ((long)row * TLEN + (long)seg * SEG) / 2 + (long)tid * F4PT;

    // ---- issue ALL 8 loads up front (MLP=8 per thread, 32 warps/SM) ----
    float4 va0 = vel4[f4base],     va1 = vel4[f4base + 1];
    float4 ca0 = cov4[f4base],     ca1 = cov4[f4base + 1];
    float4 ga0 = vgt4[f4base],     ga1 = vgt4[f4base + 1];
    float4 pa0 = pgt4[f4base],     pa1 = pgt4[f4base + 1];

    const float2 v0 = vel2[(long)row * TLEN];    // broadcast

    // ---- per-thread vel sum, then block scan of thread sums ----
    const float tsx = va0.x + va0.z + va1.x + va1.z;
    const float tsy = va0.y + va0.w + va1.y + va1.w;

    float ixp = tsx, iyp = tsy;                  // inclusive within warp
    #pragma unroll
    for (int off = 1; off < 32; off <<= 1) {
        float nx = __shfl_up_sync(0xffffffffu, ixp, off);
        float ny = __shfl_up_sync(0xffffffffu, iyp, off);
        if (lane >= off) { ixp += nx; iyp += ny; }
    }
    if (lane == 31) wsum[wid] = make_float2(ixp, iyp);
    __syncthreads();
    if (wid == 0 && lane < NWARP) {
        float sx = wsum[lane].x, sy = wsum[lane].y;
        #pragma unroll
        for (int off = 1; off < NWARP; off <<= 1) {
            float nx = __shfl_up_sync(0xffffu, sx, off);
            float ny = __shfl_up_sync(0xffffu, sy, off);
            if (lane >= off) { sx += nx; sy += ny; }
        }
        wsum[lane] = make_float2(sx, sy);
    }
    __syncthreads();

    // exclusive prefix (within segment) entering this thread's first element
    float ex = (wid > 0 ? wsum[wid - 1].x : 0.0f) + (ixp - tsx);
    float ey = (wid > 0 ? wsum[wid - 1].y : 0.0f) + (iyp - tsy);
    const float2 segsum = wsum[NWARP - 1];

    // ---- per-element math (2 MUFU per timestep: EX2 only) ----
    float sax = 0.f, say = 0.f, sa2 = 0.f;
    float lve = 0.f, lcs = 0.f, rgs = 0.f;

    #pragma unroll
    for (int i = 0; i < EPT; ++i) {
        const float vx = (i == 0) ? va0.x : (i == 1) ? va0.z : (i == 2) ? va1.x : va1.z;
        const float vy = (i == 0) ? va0.y : (i == 1) ? va0.w : (i == 2) ? va1.y : va1.w;
        const float cx = (i == 0) ? ca0.x : (i == 1) ? ca0.z : (i == 2) ? ca1.x : ca1.z;
        const float cy = (i == 0) ? ca0.y : (i == 1) ? ca0.w : (i == 2) ? ca1.y : ca1.w;
        const float gx = (i == 0) ? ga0.x : (i == 1) ? ga0.z : (i == 2) ? ga1.x : ga1.z;
        const float gy = (i == 0) ? ga0.y : (i == 1) ? ga0.w : (i == 2) ? ga1.y : ga1.w;
        const float px = (i == 0) ? pa0.x : (i == 1) ? pa0.z : (i == 2) ? pa1.x : pa1.z;
        const float py = (i == 0) ? pa0.y : (i == 1) ? pa0.w : (i == 2) ? pa1.y : pa1.w;

        // a = DT*(v0 + local_excl) - pos_gt (global carry added in tail)
        const float ax = DT_F * (v0.x + ex) - px;
        const float ay = DT_F * (v0.y + ey) - py;
        sax += ax; say += ay;
        sa2 += ax * ax + ay * ay;
        ex += vx; ey += vy;

        const float dvx = vx - gx;
        const float dvy = vy - gy;
        lve += dvx * dvx + dvy * dvy;

        // inv_sigma = 1/clip(exp(c),0.01) = min(exp(-c), 100)
        const float ivx = fminf(__expf(-cx), 100.0f);
        const float ivy = fminf(__expf(-cy), 100.0f);
        // log(sx*sy + eps) = max(cx,ln.01)+max(cy,ln.01) + log1p(u), u = eps*ivx*ivy <= 1e-2
        const float u = EPS_L * ivx * ivy;
        const float logdet = fmaxf(cx, LN_MINVAR) + fmaxf(cy, LN_MINVAR)
                           + u * (1.0f - 0.5f * u);
        lcs += ivx * dvx * dvx + ivy * dvy * dvy + logdet;
        rgs += ivx + ivy;
    }

    // ---- block reduce 6 floats ----
    float r[6] = {sax, say, sa2, lve, lcs, rgs};
    #pragma unroll
    for (int off = 16; off > 0; off >>= 1) {
        #pragma unroll
        for (int k = 0; k < 6; ++k)
            r[k] += __shfl_down_sync(0xffffffffu, r[k], off);
    }
    if (lane == 0) {
        #pragma unroll
        for (int k = 0; k < 6; ++k) sred[wid][k] = r[k];
    }
    __syncthreads();
    if (tid == 0) {
        #pragma unroll
        for (int k = 0; k < 6; ++k) {
            float s = sred[0][k];
            #pragma unroll
            for (int w = 1; w < NWARP; ++w) s += sred[w][k];
            r[k] = s;
        }
        const int ri = seg * BATCH + row;
        g_recA[ri] = make_float4(segsum.x, segsum.y, r[0], r[1]);
        g_recB[ri] = make_float4(r[2], r[3], r[4], r[5]);
        __threadfence();
        const int done = atomicAdd(&g_cnt, 1);
        s_last = (done == NGRID - 1);
    }
    __syncthreads();

    if (!s_last) return;

    // ================= tail: one block, fp64 carry recombination =================
    __threadfence();
    {
        double d[4] = {0.0, 0.0, 0.0, 0.0};
        if (tid < BATCH) {
            const int myrow = tid;
            double cxd = 0.0, cyd = 0.0;
            #pragma unroll 1
            for (int s = 0; s < NSEG; ++s) {
                const float4 ra = g_recA[s * BATCH + myrow];
                const float4 rb = g_recB[s * BATCH + myrow];
                d[0] += (double)rb.x
                      + 2.0 * DT_D * (cxd * (double)ra.z + cyd * (double)ra.w)
                      + (double)SEG * DT_D * DT_D * (cxd * cxd + cyd * cyd);
                d[1] += (double)rb.y;
                d[2] += (double)rb.z;
                d[3] += (double)rb.w;
                cxd += (double)ra.x;
                cyd += (double)ra.y;
            }
        }

        #pragma unroll
        for (int off = 16; off > 0; off >>= 1) {
            #pragma unroll
            for (int k = 0; k < 4; ++k)
                d[k] += __shfl_down_sync(0xffffffffu, d[k], off);
        }
        if (lane == 0) {
            #pragma unroll
            for (int k = 0; k < 4; ++k) dred[wid][k] = d[k];
        }
        __syncthreads();
        if (tid == 0) {
            #pragma unroll
            for (int k = 0; k < 4; ++k) {
                double s = dred[0][k];
                #pragma unroll
                for (int w = 1; w < NWARP; ++w) s += dred[w][k];
                d[k] = s;
            }
            const double n_all = (double)BATCH * (double)TLEN * 2.0;
            const double n_bt  = (double)BATCH * (double)TLEN;
            const float  ldv = *log_dv_p;
            const float  ldc = *log_dc_p;
            const double dv  = exp((double)ldv);
            const double dc  = exp((double)ldc);

            const double lv_total = (d[0] + d[1]) / n_all;
            const double lc_total = 0.5 * (d[2] / n_bt);
            const double reg      = d[3] / n_bt;

            double total = lv_total / (2.0 * dv * dv)
                         + lc_total / (2.0 * dc * dc)
                         + (double)ldv + (double)ldc
                         + REG_W * reg;
            *out = (float)total;
            g_cnt = 0;
        }
    }
}

extern "C" void kernel_launch(void* const* d_in, const int* in_sizes, int n_in,
                              void* d_out, int out_size)
{
    const float4* vel4 = (const float4*)d_in[0];
    const float4* cov4 = (const float4*)d_in[1];
    const float4* vgt4 = (const float4*)d_in[2];
    const float4* pgt4 = (const float4*)d_in[3];
    const float2* vel2 = (const float2*)d_in[0];
    const float*  ldv  = (const float*)d_in[4];
    const float*  ldc  = (const float*)d_in[5];
    float* out = (float*)d_out;

    mtl_fused_kernel<<<NGRID, NTHR>>>(vel4, cov4, vgt4, pgt4, vel2, ldv, ldc, out);
}